// round 12
// baseline (speedup 1.0000x reference)
#include <cuda_runtime.h>
#include <cuda_bf16.h>
#include <math.h>

// ---------------------------------------------------------------------------
// CfC recurrence v7 = R11 (13.32ms) scaled to 512 threads / 16 warps:
//   - staging skew (l>>2)&7 (verified conflict-free for both phases)
//   - phase A: 32-way k-split x 16 row-groups (4x4 tile, 4 k per chunk)
//   - phase B: 8-way k-split (km bits 4-6) x 16 rgB x 4 matrices (4x4 tile)
//   - epilogue/state on tid<256; orchestration R11-exact
// B=64, T=1024, D=256, H=512, BU=512, Z=768. 128 CTAs x 512 threads.
// ---------------------------------------------------------------------------

#define Bc   64
#define Tc   1024
#define Dc   256
#define Hc   512
#define ZC   768
#define NCTA 128
#define NTHR 512
#define ZROW 96
#define ZBUF (128 * ZROW)
#define WA_SEC 196
#define WB_SEC 2056
#define REDB_SEC 320
#define SMEM_FLOATS (16*WA_SEC + 4*WB_SEC + 3*ZBUF + 256 + 16*REDB_SEC)
#define SMEM_BYTES  (SMEM_FLOATS * 4)

// -------------------- device-global state ----------------------------------
__device__ unsigned g_count = 0;
__device__ unsigned g_sense = 0;
__device__ __align__(256) float g_h [Hc * Bc];    // [col][b]
__device__ __align__(256) float g_bb[Hc * Bc];    // [col][b]
__device__ __align__(256) float g_xT[(size_t)Tc * Dc * Bc];   // [t][d][b]

// ------------------------------- helpers -----------------------------------
__device__ __forceinline__ void cp16(float* dst_smem, const float* src_gmem) {
    unsigned d = (unsigned)__cvta_generic_to_shared(dst_smem);
    asm volatile("cp.async.cg.shared.global [%0], [%1], 16;"
                 :: "r"(d), "l"(src_gmem) : "memory");
}
__device__ __forceinline__ void cp_commit() {
    asm volatile("cp.async.commit_group;" ::: "memory");
}
template <int N>
__device__ __forceinline__ void cp_wait() {
    asm volatile("cp.async.wait_group %0;" :: "n"(N) : "memory");
}

__device__ __forceinline__ void ffma2(unsigned long long& d,
                                      unsigned long long a,
                                      unsigned long long b) {
    asm("fma.rn.f32x2 %0, %1, %2, %0;" : "+l"(d) : "l"(a), "l"(b));
}
__device__ __forceinline__ void add2(unsigned long long& d,
                                     unsigned long long a,
                                     unsigned long long b) {
    asm("add.rn.f32x2 %0, %1, %2;" : "=l"(d) : "l"(a), "l"(b));
}
__device__ __forceinline__ unsigned long long dup2(float v) {
    unsigned long long r; unsigned u = __float_as_uint(v);
    asm("mov.b64 %0, {%1, %1};" : "=l"(r) : "r"(u));
    return r;
}
__device__ __forceinline__ float lo2(unsigned long long v) {
    return __uint_as_float((unsigned)v);
}
__device__ __forceinline__ float hi2(unsigned long long v) {
    return __uint_as_float((unsigned)(v >> 32));
}

__device__ __forceinline__ void mac16(unsigned long long* acc, float4 z,
                                      ulonglong2 w) {
    unsigned long long zz;
    zz = dup2(z.x); ffma2(acc[0], zz, w.x); ffma2(acc[1], zz, w.y);
    zz = dup2(z.y); ffma2(acc[2], zz, w.x); ffma2(acc[3], zz, w.y);
    zz = dup2(z.z); ffma2(acc[4], zz, w.x); ffma2(acc[5], zz, w.y);
    zz = dup2(z.w); ffma2(acc[6], zz, w.x); ffma2(acc[7], zz, w.y);
}

// ---- monolithic split global barrier (R8/R11 proven) ----
__device__ __forceinline__ void gbar_arrive(unsigned sense0, unsigned& ep) {
    __syncthreads();
    ep++;
    if (threadIdx.x == 0) {
        __threadfence();
        if (atomicAdd(&g_count, 1u) == (unsigned)(NCTA - 1)) {
            atomicExch(&g_count, 0u);
            asm volatile("st.release.gpu.u32 [%0], %1;"
                         :: "l"(&g_sense), "r"(sense0 + ep) : "memory");
        }
    }
}
__device__ __forceinline__ void gbar_wait(unsigned sense0, unsigned ep) {
    if (threadIdx.x == 0) {
        unsigned v, target = sense0 + ep;
        do {
            asm volatile("ld.acquire.gpu.u32 %0, [%1];"
                         : "=r"(v) : "l"(&g_sense) : "memory");
        } while (v != target);
    }
    __syncthreads();
}

// Stage one 128-row k-chunk; skew per 4-row group: (l>>2)&7.
__device__ __forceinline__ void stage_chunk(float* buf,
                                            const float* __restrict__ src) {
    int tid = threadIdx.x;
#pragma unroll
    for (int i = 0; i < 4; i++) {
        int lin = tid + i * NTHR;           // 0..2047
        int l   = lin >> 4;                 // row 0..127
        int b4  = (lin & 15) << 2;          // float4 col
        cp16(buf + l * ZROW + (((l >> 2) & 7) << 2) + b4,
             src + l * Bc + b4);
    }
    cp_commit();
}

// Phase A: one chunk, 4 k per thread (rows ks5*4 .. +3), 4x4 tile.
// skew = ((ks5*4+i)>>2)&7 = ks5&7 for i<4 (constant per thread).
__device__ __forceinline__ void gemmA_chunk(const float* __restrict__ buf,
                                            const float* __restrict__ s_wA,
                                            int ch, int ks5, int rgA,
                                            unsigned long long* acc) {
    const float* zp = buf + (ks5 * 4) * ZROW + ((ks5 & 7) << 2) + (rgA << 2);
    const float* wp = s_wA + (ks5 >> 1) * WA_SEC
                    + (ch * 8 + (ks5 & 1) * 4) * 4;
#pragma unroll
    for (int i = 0; i < 4; i++) {
        float4 z = *(const float4*)(zp + i * ZROW);
        ulonglong2 w = *(const ulonglong2*)(wp + i * 4);
        mac16(acc, z, w);
    }
}

// Phase B: one chunk, 16 k per thread (rows km*16 .. +15), 4x4 tile.
__device__ __forceinline__ void gemmB_chunk(const float* __restrict__ buf,
                                            const float* __restrict__ s_wB,
                                            int ch, int km, int rgB, int mB,
                                            unsigned long long* acc) {
#pragma unroll
    for (int j = 0; j < 2; j++) {
        int row0 = km * 16 + j * 8;
        const float* zp = buf + row0 * ZROW + (rgB << 2);
        const float* wp = s_wB + (row0 >> 5) * WB_SEC
                        + (ch * 32 + (row0 & 31)) * 16 + mB * 4;
#pragma unroll
        for (int i = 0; i < 8; i++) {
            int skew = ((row0 + i) >> 2) & 7;
            float4 z = *(const float4*)(zp + i * ZROW + (skew << 2));
            ulonglong2 w = *(const ulonglong2*)(wp + i * 16);
            mac16(acc, z, w);
        }
    }
}

// ------------------------- x transpose kernel ------------------------------
__global__ void __launch_bounds__(256) xpose_kernel(const float* __restrict__ x) {
    __shared__ float tile[32 * 65];
    int t = blockIdx.x;
    int tid = threadIdx.x;
    for (int dblk = 0; dblk < 8; dblk++) {
        int dl = tid & 31, bq = tid >> 5;
#pragma unroll
        for (int b8 = 0; b8 < 8; b8++) {
            int b = bq * 8 + b8;
            tile[dl * 65 + b] = x[((size_t)b * Tc + t) * Dc + dblk * 32 + dl];
        }
        __syncthreads();
        int b = tid & 63, dq = tid >> 6;
#pragma unroll
        for (int j = 0; j < 8; j++) {
            int d = dq * 8 + j;
            g_xT[((size_t)t * Dc + dblk * 32 + d) * Bc + b] = tile[d * 65 + b];
        }
        __syncthreads();
    }
}

// --------------------------------- kernel ----------------------------------
__global__ void __launch_bounds__(NTHR, 1)
cfc_persistent_kernel(const float* __restrict__ ts,
                      const float* __restrict__ h0,  const float* __restrict__ s0,
                      const float* __restrict__ Wbb, const float* __restrict__ bbb,
                      const float* __restrict__ Wff1,const float* __restrict__ bff1,
                      const float* __restrict__ Wff2,const float* __restrict__ bff2,
                      const float* __restrict__ Wta, const float* __restrict__ bta,
                      const float* __restrict__ Wtb, const float* __restrict__ btb,
                      float* __restrict__ out) {
    extern __shared__ float smem[];
    float* s_wA   = smem;                       // 16 x 196
    float* s_wB   = s_wA + 16 * WA_SEC;         // 4 x 2056
    float* s_z    = s_wB + 4 * WB_SEC;          // 3 x ZBUF
    float* s_redA = s_z + 3 * ZBUF;             // 256
    float* s_redB = s_redA + 256;               // 16 x 320

    const int tid = threadIdx.x;
    const int c0  = blockIdx.x * 4;
    const int lane = tid & 31, warp = tid >> 5;
    // phase A ids: 32-way ksplit, rgA = warp
    const int ks5 = lane, rgA = warp;
    // phase B ids
    const int rgB = tid & 15, km = (tid >> 4) & 7, mB = tid >> 7;
    // epilogue ids (tid < 256 only)
    const int ec = tid & 3, eb = tid >> 2;
    const int cg = c0 + ec;
    const int eidxA = ((eb >> 2) << 4) + ((eb & 3) << 2) + ec;
    const int eoffB = (eb >> 2) * 20 + (eb & 3) * 4 + ec;

    // ---- one-time: weights -> sectioned SMEM (R11-exact layouts) ----
    for (int idx = tid; idx < ZC * 4; idx += NTHR) {
        int k = idx >> 2, cc = idx & 3;
        int sec = (k & 127) >> 3, ch = k >> 7, i = k & 7;
        s_wA[sec * WA_SEC + (ch * 8 + i) * 4 + cc] =
            __ldg(Wbb + (size_t)k * Hc + c0 + cc);
    }
    {
        const float* Wm[4] = {Wff1, Wff2, Wta, Wtb};
#pragma unroll
        for (int m = 0; m < 4; m++)
            for (int idx = tid; idx < Hc * 4; idx += NTHR) {
                int k = idx >> 2, cc = idx & 3;
                int sec = (k & 127) >> 5, ch = k >> 7, i = k & 31;
                s_wB[sec * WB_SEC + (ch * 32 + i) * 16 + m * 4 + cc] =
                    __ldg(Wm[m] + (size_t)k * Hc + c0 + cc);
            }
    }
    const float bbbc = __ldg(bbb  + cg);
    const float bf1c = __ldg(bff1 + cg);
    const float bf2c = __ldg(bff2 + cg);
    const float btac = __ldg(bta  + cg);
    const float btbc = __ldg(btb  + cg);

    float s_state = 0.0f;
    if (tid < 256) {
        s_state = __ldg(s0 + (size_t)eb * Hc + cg);
        g_h[cg * Bc + eb] = __ldg(h0 + (size_t)eb * Hc + cg);
    }

    float* b0 = s_z;
    float* b1 = s_z + ZBUF;
    float* b2 = s_z + 2 * ZBUF;

    unsigned sense0 = 0, ep = 0;
    if (tid == 0) {
        asm volatile("ld.acquire.gpu.u32 %0, [%1];"
                     : "=r"(sense0) : "l"(&g_sense) : "memory");
    }

    gbar_arrive(sense0, ep);                    // publish h0
    stage_chunk(b2, g_xT);                      // X0 -> b2
    stage_chunk(b0, g_xT + (size_t)128 * Bc);   // X1 -> b0

    for (int t = 0; t < Tc; t++) {
        // ============ Phase A: bb = silu(z @ Wbb + bbb), K=768 ============
        unsigned long long acc[8] = {0,0,0,0,0,0,0,0};
        cp_wait<1>(); __syncthreads();
        gemmA_chunk(b2, s_wA, 0, ks5, rgA, acc);             // X0
        cp_wait<0>(); __syncthreads();
        gemmA_chunk(b0, s_wA, 1, ks5, rgA, acc);             // X1
        gbar_wait(sense0, ep);                  // h(t) visible chip-wide
        stage_chunk(b1, g_h);                   // H0
        stage_chunk(b2, g_h + 128 * Bc);        // H1
        stage_chunk(b0, g_h + 256 * Bc);        // H2
        cp_wait<2>(); __syncthreads();
        gemmA_chunk(b1, s_wA, 2, ks5, rgA, acc);             // H0
        __syncthreads();
        stage_chunk(b1, g_h + 384 * Bc);        // H3
        cp_wait<2>(); __syncthreads();
        gemmA_chunk(b2, s_wA, 3, ks5, rgA, acc);             // H1
        cp_wait<1>(); __syncthreads();
        gemmA_chunk(b0, s_wA, 4, ks5, rgA, acc);             // H2
        cp_wait<0>(); __syncthreads();
        gemmA_chunk(b1, s_wA, 5, ks5, rgA, acc);             // H3

        // reduce 32-way ksplit (lane bits 0..4)
#pragma unroll
        for (int d = 1; d <= 16; d <<= 1)
#pragma unroll
            for (int q = 0; q < 8; q++) {
                unsigned long long o = __shfl_xor_sync(0xffffffffu, acc[q], d);
                add2(acc[q], acc[q], o);
            }
        if (lane == 0) {
            float* dst = s_redA + rgA * 16;
#pragma unroll
            for (int r = 0; r < 4; r++) {
                float4 v = make_float4(lo2(acc[2*r]), hi2(acc[2*r]),
                                       lo2(acc[2*r+1]), hi2(acc[2*r+1]));
                *(float4*)(dst + r * 4) = v;
            }
        }
        __syncthreads();
        if (tid < 256) {
            float av  = s_redA[eidxA] + bbbc;
            float bbv = av / (1.0f + expf(-av));       // silu
            g_bb[cg * Bc + eb] = bbv;
        }
        gbar_arrive(sense0, ep);                        // bb barrier
        float wts = 0.0f;
        if (tid < 256) {
            float tstv = __ldg(ts + (size_t)eb * Tc + t);
            float tn   = 1.0f / tstv;
            wts = (tn > 0.0f) ? expf(tn * (1.0f - 2.0f * logf(tn))) : 0.0f;
        }
        gbar_wait(sense0, ep);

        // ====== Phase B: 4 GEMMs over bb (K=512); gate & update ======
        unsigned long long fac[8] = {0,0,0,0,0,0,0,0};
        const int t1 = (t + 1 < Tc) ? t + 1 : t;
        stage_chunk(b2, g_bb);                   // B0
        stage_chunk(b0, g_bb + 128 * Bc);        // B1
        stage_chunk(b1, g_bb + 256 * Bc);        // B2
        cp_wait<2>(); __syncthreads();
        gemmB_chunk(b2, s_wB, 0, km, rgB, mB, fac);
        __syncthreads();
        stage_chunk(b2, g_bb + 384 * Bc);        // B3
        cp_wait<2>(); __syncthreads();
        gemmB_chunk(b0, s_wB, 1, km, rgB, mB, fac);
        __syncthreads();
        stage_chunk(b0, g_xT + ((size_t)t1 * Dc) * Bc);         // X0(t+1)
        cp_wait<2>(); __syncthreads();
        gemmB_chunk(b1, s_wB, 2, km, rgB, mB, fac);
        __syncthreads();
        stage_chunk(b1, g_xT + ((size_t)t1 * Dc + 128) * Bc);   // X1(t+1)
        cp_wait<2>(); __syncthreads();
        gemmB_chunk(b2, s_wB, 3, km, rgB, mB, fac);
        // outstanding: X0(t+1), X1(t+1) — matches loop entry

        // reduce km bit0 (lane bit 4), then SMEM combine over km bits 1-2
#pragma unroll
        for (int q = 0; q < 8; q++) {
            unsigned long long o = __shfl_xor_sync(0xffffffffu, fac[q], 16);
            add2(fac[q], fac[q], o);
        }
        if (lane < 16) {
            // kmHigh = warp & 3, mB = warp >> 2, rgB = lane
            float* dst = s_redB + ((warp & 3) * 4 + (warp >> 2)) * REDB_SEC
                       + lane * 20;
#pragma unroll
            for (int r = 0; r < 4; r++) {
                float4 v = make_float4(lo2(fac[2*r]), hi2(fac[2*r]),
                                       lo2(fac[2*r+1]), hi2(fac[2*r+1]));
                *(float4*)(dst + r * 4) = v;
            }
        }
        __syncthreads();
        if (tid < 256) {
            float p0 = 0.f, p1 = 0.f, p2 = 0.f, p3 = 0.f;
#pragma unroll
            for (int kh = 0; kh < 4; kh++) {
                p0 += s_redB[(kh * 4 + 0) * REDB_SEC + eoffB];
                p1 += s_redB[(kh * 4 + 1) * REDB_SEC + eoffB];
                p2 += s_redB[(kh * 4 + 2) * REDB_SEC + eoffB];
                p3 += s_redB[(kh * 4 + 3) * REDB_SEC + eoffB];
            }
            float ff1 = tanhf(p0 + bf1c);
            float ff2 = tanhf(p1 + bf2c);
            s_state += (p2 + btac) * wts + (p3 + btbc);
            float ti = 1.0f / (1.0f + expf(-s_state));
            float hn = ff1 + ti * (ff2 - ff1);
            g_h[cg * Bc + eb] = hn;
            out[((size_t)eb * Tc + t) * Hc + cg] = hn;
        }
        gbar_arrive(sense0, ep);                        // h barrier
        // rotate: X0(t+1)=old b0 -> new b2, X1(t+1)=old b1 -> new b0
        float* tmp = b2; b2 = b0; b0 = b1; b1 = tmp;
    }
    cp_wait<0>();
}

// --------------------------------- launch ----------------------------------
extern "C" void kernel_launch(void* const* d_in, const int* in_sizes, int n_in,
                              void* d_out, int out_size) {
    (void)in_sizes; (void)n_in; (void)out_size;
    cudaFuncSetAttribute(cfc_persistent_kernel,
                         cudaFuncAttributeMaxDynamicSharedMemorySize, SMEM_BYTES);
    xpose_kernel<<<Tc, 256>>>((const float*)d_in[0]);
    cfc_persistent_kernel<<<NCTA, NTHR, SMEM_BYTES>>>(
        (const float*)d_in[1],
        (const float*)d_in[2],  (const float*)d_in[3],
        (const float*)d_in[4],  (const float*)d_in[5],
        (const float*)d_in[6],  (const float*)d_in[7],
        (const float*)d_in[8],  (const float*)d_in[9],
        (const float*)d_in[10], (const float*)d_in[11],
        (const float*)d_in[12], (const float*)d_in[13],
        (float*)d_out);
}

// round 13
// speedup vs baseline: 1.0595x; 1.0595x over previous
#include <cuda_runtime.h>
#include <cuda_bf16.h>
#include <math.h>

// ---------------------------------------------------------------------------
// CfC recurrence v8 = R11 (13.32ms, 256 thr) with the two in-loop global
// barriers replaced by producer-quarter dataflow counters:
//   - g_cntH[4] / g_cntB[4]: 32 CTAs arrive per quarter per step (thread 0,
//     threadfence + atomicAdd)
//   - staging of chunk q gated on counter q only (lane0-per-warp poll)
//   - per-CTA rotated chunk order (start at own quarter)
// GEMM tiles, layouts, staging, reductions: R11-verbatim.
// B=64, T=1024, D=256, H=512, BU=512, Z=768. 128 CTAs x 256 threads.
// ---------------------------------------------------------------------------

#define Bc   64
#define Tc   1024
#define Dc   256
#define Hc   512
#define ZC   768
#define NCTA 128
#define NTHR 256
#define ZROW 96
#define ZBUF (128 * ZROW)
#define WA_SEC 196
#define WB_SEC 2056
#define REDB_SEC 320
#define SMEM_FLOATS (16*WA_SEC + 4*WB_SEC + 3*ZBUF + 256 + 8*REDB_SEC)
#define SMEM_BYTES  (SMEM_FLOATS * 4)

// -------------------- device-global state ----------------------------------
__device__ unsigned g_count = 0;          // init barrier only
__device__ unsigned g_sense = 0;
__device__ unsigned g_cntH[4];            // h quarter epochs (monotonic)
__device__ unsigned g_cntB[4];            // bb quarter epochs (monotonic)
__device__ __align__(256) float g_h [Hc * Bc];    // [col][b]
__device__ __align__(256) float g_bb[Hc * Bc];    // [col][b]
__device__ __align__(256) float g_xT[(size_t)Tc * Dc * Bc];   // [t][d][b]

// ------------------------------- helpers -----------------------------------
__device__ __forceinline__ void cp16(float* dst_smem, const float* src_gmem) {
    unsigned d = (unsigned)__cvta_generic_to_shared(dst_smem);
    asm volatile("cp.async.cg.shared.global [%0], [%1], 16;"
                 :: "r"(d), "l"(src_gmem) : "memory");
}
__device__ __forceinline__ void cp_commit() {
    asm volatile("cp.async.commit_group;" ::: "memory");
}
template <int N>
__device__ __forceinline__ void cp_wait() {
    asm volatile("cp.async.wait_group %0;" :: "n"(N) : "memory");
}

__device__ __forceinline__ void ffma2(unsigned long long& d,
                                      unsigned long long a,
                                      unsigned long long b) {
    asm("fma.rn.f32x2 %0, %1, %2, %0;" : "+l"(d) : "l"(a), "l"(b));
}
__device__ __forceinline__ void add2(unsigned long long& d,
                                     unsigned long long a,
                                     unsigned long long b) {
    asm("add.rn.f32x2 %0, %1, %2;" : "=l"(d) : "l"(a), "l"(b));
}
__device__ __forceinline__ unsigned long long dup2(float v) {
    unsigned long long r; unsigned u = __float_as_uint(v);
    asm("mov.b64 %0, {%1, %1};" : "=l"(r) : "r"(u));
    return r;
}
__device__ __forceinline__ float lo2(unsigned long long v) {
    return __uint_as_float((unsigned)v);
}
__device__ __forceinline__ float hi2(unsigned long long v) {
    return __uint_as_float((unsigned)(v >> 32));
}

__device__ __forceinline__ void mac16(unsigned long long* acc, float4 z,
                                      ulonglong2 w) {
    unsigned long long zz;
    zz = dup2(z.x); ffma2(acc[0], zz, w.x); ffma2(acc[1], zz, w.y);
    zz = dup2(z.y); ffma2(acc[2], zz, w.x); ffma2(acc[3], zz, w.y);
    zz = dup2(z.z); ffma2(acc[4], zz, w.x); ffma2(acc[5], zz, w.y);
    zz = dup2(z.w); ffma2(acc[6], zz, w.x); ffma2(acc[7], zz, w.y);
}

// ---- init-only monolithic barrier (R8/R11 proven) ----
__device__ __forceinline__ void gbar(unsigned sense0, unsigned& ep) {
    __syncthreads();
    ep++;
    if (threadIdx.x == 0) {
        __threadfence();
        if (atomicAdd(&g_count, 1u) == (unsigned)(NCTA - 1)) {
            atomicExch(&g_count, 0u);
            asm volatile("st.release.gpu.u32 [%0], %1;"
                         :: "l"(&g_sense), "r"(sense0 + ep) : "memory");
        }
        unsigned v, target = sense0 + ep;
        do {
            asm volatile("ld.acquire.gpu.u32 %0, [%1];"
                         : "=r"(v) : "l"(&g_sense) : "memory");
        } while (v != target);
    }
    __syncthreads();
}

// ---- quarter counters ----
__device__ __forceinline__ void quarter_arrive(unsigned* cnt) {
    __syncthreads();                     // CTA's stores done
    if (threadIdx.x == 0) {
        __threadfence();                 // release to L2
        atomicAdd(cnt, 1u);
    }
}
__device__ __forceinline__ unsigned ldacq(const unsigned* p) {
    unsigned v;
    asm volatile("ld.acquire.gpu.u32 %0, [%1];" : "=r"(v) : "l"(p) : "memory");
    return v;
}

// Stage one 128-row k-chunk (R11-exact: coalesced, row-group skew).
__device__ __forceinline__ void stage_chunk(float* buf,
                                            const float* __restrict__ src) {
    int tid = threadIdx.x;
#pragma unroll
    for (int i = 0; i < 8; i++) {
        int lin = tid + i * NTHR;           // 0..2047
        int l   = lin >> 4;                 // row 0..127
        int b4  = (lin & 15) << 2;          // float4 col
        cp16(buf + l * ZROW + (((l >> 3) & 7) << 2) + b4,
             src + l * Bc + b4);
    }
    cp_commit();
}

// Gated stage: lane0 of each warp polls the quarter counter first.
__device__ __forceinline__ void stage_gated(float* buf,
                                            const float* __restrict__ src,
                                            const unsigned* cnt, unsigned tgt) {
    if ((threadIdx.x & 31) == 0) {
        unsigned v;
        do { v = ldacq(cnt); } while ((int)(v - tgt) < 0);
    }
    __syncwarp();
    stage_chunk(buf, src);
}

// Phase A: one chunk (8 k per thread), 4x4 tile (R11-exact).
__device__ __forceinline__ void gemmA_chunk(const float* __restrict__ buf,
                                            const float* __restrict__ wsec,
                                            int ks2, int rgA,
                                            unsigned long long* acc) {
    const float* zp = buf + (ks2 * 8) * ZROW + ((ks2 & 7) << 2) + (rgA << 2);
#pragma unroll
    for (int i = 0; i < 8; i++) {
        float4 z = *(const float4*)(zp + i * ZROW);
        ulonglong2 w = *(const ulonglong2*)(wsec + i * 4);
        mac16(acc, z, w);
    }
}

// Phase B: one chunk (32 k per thread), 4x4 tile (R11-exact, rgB low bits).
__device__ __forceinline__ void gemmB_chunk(const float* __restrict__ buf,
                                            const float* __restrict__ wsec,
                                            int km, int rgB,
                                            unsigned long long* acc) {
    const float* zb = buf + (km * 32) * ZROW + (rgB << 2);
#pragma unroll
    for (int j = 0; j < 4; j++) {
        const float* zp = zb + (j * 8) * ZROW + ((((km << 2) + j) & 7) << 2);
        const float* wp = wsec + j * 128;
#pragma unroll
        for (int i = 0; i < 8; i++) {
            float4 z = *(const float4*)(zp + i * ZROW);
            ulonglong2 w = *(const ulonglong2*)(wp + i * 16);
            mac16(acc, z, w);
        }
    }
}

// ------------------------- x transpose kernel ------------------------------
__global__ void __launch_bounds__(256) xpose_kernel(const float* __restrict__ x) {
    __shared__ float tile[32 * 65];
    int t = blockIdx.x;
    int tid = threadIdx.x;
    for (int dblk = 0; dblk < 8; dblk++) {
        int dl = tid & 31, bq = tid >> 5;
#pragma unroll
        for (int b8 = 0; b8 < 8; b8++) {
            int b = bq * 8 + b8;
            tile[dl * 65 + b] = x[((size_t)b * Tc + t) * Dc + dblk * 32 + dl];
        }
        __syncthreads();
        int b = tid & 63, dq = tid >> 6;
#pragma unroll
        for (int j = 0; j < 8; j++) {
            int d = dq * 8 + j;
            g_xT[((size_t)t * Dc + dblk * 32 + d) * Bc + b] = tile[d * 65 + b];
        }
        __syncthreads();
    }
}

// --------------------------------- kernel ----------------------------------
__global__ void __launch_bounds__(NTHR, 1)
cfc_persistent_kernel(const float* __restrict__ ts,
                      const float* __restrict__ h0,  const float* __restrict__ s0,
                      const float* __restrict__ Wbb, const float* __restrict__ bbb,
                      const float* __restrict__ Wff1,const float* __restrict__ bff1,
                      const float* __restrict__ Wff2,const float* __restrict__ bff2,
                      const float* __restrict__ Wta, const float* __restrict__ bta,
                      const float* __restrict__ Wtb, const float* __restrict__ btb,
                      float* __restrict__ out) {
    extern __shared__ float smem[];
    float* s_wA   = smem;                       // 16 x 196
    float* s_wB   = s_wA + 16 * WA_SEC;         // 4 x 2056
    float* s_z    = s_wB + 4 * WB_SEC;          // 3 x ZBUF
    float* s_redA = s_z + 3 * ZBUF;             // 256
    float* s_redB = s_redA + 256;               // 8 x 320

    const int tid = threadIdx.x;
    const int bid = blockIdx.x;
    const int c0  = bid * 4;
    const int lane = tid & 31, warp = tid >> 5;
    const int ks2 = tid & 15, rgA = tid >> 4;                      // phase A
    const int rgB = tid & 15, km = (tid >> 4) & 3, mB = tid >> 6;  // phase B
    const int ec = tid & 3, eb = tid >> 2;                         // epilogue
    const int cg = c0 + ec;
    const int eidxA = ((eb >> 2) << 4) + ((eb & 3) << 2) + ec;
    const int eoffB = (eb >> 2) * 20 + (eb & 3) * 4 + ec;
    const int myq = bid >> 5;                   // own quarter
    const int qa = myq, qb = (myq + 1) & 3, qc = (myq + 2) & 3,
              qd = (myq + 3) & 3;

    // counter bases (all counters equal at rest; read before init barrier)
    const unsigned baseH = ldacq(&g_cntH[0]);
    const unsigned baseB = ldacq(&g_cntB[0]);

    // ---- one-time: weights -> sectioned SMEM (R11-exact layouts) ----
    for (int idx = tid; idx < ZC * 4; idx += NTHR) {
        int k = idx >> 2, cc = idx & 3;
        int sec = (k & 127) >> 3, ch = k >> 7, i = k & 7;
        s_wA[sec * WA_SEC + (ch * 8 + i) * 4 + cc] =
            __ldg(Wbb + (size_t)k * Hc + c0 + cc);
    }
    {
        const float* Wm[4] = {Wff1, Wff2, Wta, Wtb};
#pragma unroll
        for (int m = 0; m < 4; m++)
            for (int idx = tid; idx < Hc * 4; idx += NTHR) {
                int k = idx >> 2, cc = idx & 3;
                int sec = (k & 127) >> 5, ch = k >> 7, i = k & 31;
                s_wB[sec * WB_SEC + (ch * 32 + i) * 16 + m * 4 + cc] =
                    __ldg(Wm[m] + (size_t)k * Hc + c0 + cc);
            }
    }
    const float bbbc = __ldg(bbb  + cg);
    const float bf1c = __ldg(bff1 + cg);
    const float bf2c = __ldg(bff2 + cg);
    const float btac = __ldg(bta  + cg);
    const float btbc = __ldg(btb  + cg);

    float s_state = __ldg(s0 + (size_t)eb * Hc + cg);
    g_h[cg * Bc + eb] = __ldg(h0 + (size_t)eb * Hc + cg);

    float* b0 = s_z;
    float* b1 = s_z + ZBUF;
    float* b2 = s_z + 2 * ZBUF;

    unsigned sense0 = 0, ep = 0;
    if (tid == 0) sense0 = ldacq(&g_sense);

    // init barrier: all CTAs have read bases AND h0 is visible chip-wide
    gbar(sense0, ep);

    // prefetch x(0): X0 -> b2, X1 -> b0
    stage_chunk(b2, g_xT);
    stage_chunk(b0, g_xT + (size_t)128 * Bc);

    for (int t = 0; t < Tc; t++) {
        const unsigned tgtH = baseH + 32u * (unsigned)t;        // h(t) ready
        const unsigned tgtB = baseB + 32u * (unsigned)(t + 1);  // bb(t) ready

        // ============ Phase A: bb = silu(z @ Wbb + bbb), K=768 ============
        unsigned long long acc[8] = {0,0,0,0,0,0,0,0};
        cp_wait<1>(); __syncthreads();
        gemmA_chunk(b2, s_wA + ks2 * WA_SEC + 0 * 32, ks2, rgA, acc);  // X0
        cp_wait<0>(); __syncthreads();
        gemmA_chunk(b0, s_wA + ks2 * WA_SEC + 1 * 32, ks2, rgA, acc);  // X1
        // gated h staging, rotated to start at own quarter
        stage_gated(b1, g_h + qa * 128 * Bc, g_cntH + qa, tgtH);
        stage_gated(b2, g_h + qb * 128 * Bc, g_cntH + qb, tgtH);
        stage_gated(b0, g_h + qc * 128 * Bc, g_cntH + qc, tgtH);
        cp_wait<2>(); __syncthreads();
        gemmA_chunk(b1, s_wA + ks2 * WA_SEC + (2 + qa) * 32, ks2, rgA, acc);
        __syncthreads();
        stage_gated(b1, g_h + qd * 128 * Bc, g_cntH + qd, tgtH);
        cp_wait<2>(); __syncthreads();
        gemmA_chunk(b2, s_wA + ks2 * WA_SEC + (2 + qb) * 32, ks2, rgA, acc);
        cp_wait<1>(); __syncthreads();
        gemmA_chunk(b0, s_wA + ks2 * WA_SEC + (2 + qc) * 32, ks2, rgA, acc);
        cp_wait<0>(); __syncthreads();
        gemmA_chunk(b1, s_wA + ks2 * WA_SEC + (2 + qd) * 32, ks2, rgA, acc);

        // reduce 16-way ksplit (lane bits 0..3) — R11-exact
#pragma unroll
        for (int d = 1; d <= 8; d <<= 1)
#pragma unroll
            for (int q = 0; q < 8; q++) {
                unsigned long long o = __shfl_xor_sync(0xffffffffu, acc[q], d);
                add2(acc[q], acc[q], o);
            }
        if ((tid & 15) == 0) {
            float* dst = s_redA + rgA * 16;
#pragma unroll
            for (int r = 0; r < 4; r++) {
                float4 v = make_float4(lo2(acc[2*r]), hi2(acc[2*r]),
                                       lo2(acc[2*r+1]), hi2(acc[2*r+1]));
                *(float4*)(dst + r * 4) = v;
            }
        }
        __syncthreads();
        {
            float av  = s_redA[eidxA] + bbbc;
            float bbv = av / (1.0f + expf(-av));       // silu
            g_bb[cg * Bc + eb] = bbv;
        }
        quarter_arrive(g_cntB + myq);                  // bb quarter published

        float tstv = __ldg(ts + (size_t)eb * Tc + t);
        float tn   = 1.0f / tstv;
        float wts  = (tn > 0.0f) ? expf(tn * (1.0f - 2.0f * logf(tn))) : 0.0f;

        // ====== Phase B: 4 GEMMs over bb (K=512); gate & update ======
        unsigned long long fac[8] = {0,0,0,0,0,0,0,0};
        const int t1 = (t + 1 < Tc) ? t + 1 : t;
        stage_gated(b2, g_bb + qa * 128 * Bc, g_cntB + qa, tgtB);
        stage_gated(b0, g_bb + qb * 128 * Bc, g_cntB + qb, tgtB);
        stage_gated(b1, g_bb + qc * 128 * Bc, g_cntB + qc, tgtB);
        cp_wait<2>(); __syncthreads();
        gemmB_chunk(b2, s_wB + km * WB_SEC + qa * 512 + mB * 4, km, rgB, fac);
        __syncthreads();
        stage_gated(b2, g_bb + qd * 128 * Bc, g_cntB + qd, tgtB);
        cp_wait<2>(); __syncthreads();
        gemmB_chunk(b0, s_wB + km * WB_SEC + qb * 512 + mB * 4, km, rgB, fac);
        __syncthreads();
        stage_chunk(b0, g_xT + ((size_t)t1 * Dc) * Bc);         // X0(t+1)
        cp_wait<2>(); __syncthreads();
        gemmB_chunk(b1, s_wB + km * WB_SEC + qc * 512 + mB * 4, km, rgB, fac);
        __syncthreads();
        stage_chunk(b1, g_xT + ((size_t)t1 * Dc + 128) * Bc);   // X1(t+1)
        cp_wait<2>(); __syncthreads();
        gemmB_chunk(b2, s_wB + km * WB_SEC + qd * 512 + mB * 4, km, rgB, fac);
        // outstanding: X0(t+1), X1(t+1) — matches loop entry

        // reduce km bit0 (lane bit 4), padded SMEM combine — R11-exact
#pragma unroll
        for (int q = 0; q < 8; q++) {
            unsigned long long o = __shfl_xor_sync(0xffffffffu, fac[q], 16);
            add2(fac[q], fac[q], o);
        }
        if (lane < 16) {
            float* dst = s_redB + ((warp & 1) * 4 + (warp >> 1)) * REDB_SEC
                       + lane * 20;
#pragma unroll
            for (int r = 0; r < 4; r++) {
                float4 v = make_float4(lo2(fac[2*r]), hi2(fac[2*r]),
                                       lo2(fac[2*r+1]), hi2(fac[2*r+1]));
                *(float4*)(dst + r * 4) = v;
            }
        }
        __syncthreads();
        {
            float p0 = s_redB[(0*4 + 0) * REDB_SEC + eoffB]
                     + s_redB[(1*4 + 0) * REDB_SEC + eoffB];
            float p1 = s_redB[(0*4 + 1) * REDB_SEC + eoffB]
                     + s_redB[(1*4 + 1) * REDB_SEC + eoffB];
            float p2 = s_redB[(0*4 + 2) * REDB_SEC + eoffB]
                     + s_redB[(1*4 + 2) * REDB_SEC + eoffB];
            float p3 = s_redB[(0*4 + 3) * REDB_SEC + eoffB]
                     + s_redB[(1*4 + 3) * REDB_SEC + eoffB];
            float ff1 = tanhf(p0 + bf1c);
            float ff2 = tanhf(p1 + bf2c);
            s_state += (p2 + btac) * wts + (p3 + btbc);
            float ti = 1.0f / (1.0f + expf(-s_state));
            float hn = ff1 + ti * (ff2 - ff1);
            g_h[cg * Bc + eb] = hn;
            out[((size_t)eb * Tc + t) * Hc + cg] = hn;
        }
        quarter_arrive(g_cntH + myq);                  // h(t+1) published
        // rotate: X0(t+1)=old b0 -> new b2, X1(t+1)=old b1 -> new b0
        float* tmp = b2; b2 = b0; b0 = b1; b1 = tmp;
    }
    cp_wait<0>();
}

// --------------------------------- launch ----------------------------------
extern "C" void kernel_launch(void* const* d_in, const int* in_sizes, int n_in,
                              void* d_out, int out_size) {
    (void)in_sizes; (void)n_in; (void)out_size;
    cudaFuncSetAttribute(cfc_persistent_kernel,
                         cudaFuncAttributeMaxDynamicSharedMemorySize, SMEM_BYTES);
    xpose_kernel<<<Tc, 256>>>((const float*)d_in[0]);
    cfc_persistent_kernel<<<NCTA, NTHR, SMEM_BYTES>>>(
        (const float*)d_in[1],
        (const float*)d_in[2],  (const float*)d_in[3],
        (const float*)d_in[4],  (const float*)d_in[5],
        (const float*)d_in[6],  (const float*)d_in[7],
        (const float*)d_in[8],  (const float*)d_in[9],
        (const float*)d_in[10], (const float*)d_in[11],
        (const float*)d_in[12], (const float*)d_in[13],
        (float*)d_out);
}

// round 14
// speedup vs baseline: 1.3793x; 1.3019x over previous
#include <cuda_runtime.h>
#include <cuda_bf16.h>
#include <math.h>

// ---------------------------------------------------------------------------
// CfC recurrence v9 = R11 (13.32ms) with:
//   - fused-pair chunk schedule on a fixed 5-buffer ring (syncs 15 -> 11/step)
//   - 64-float staged rows + XOR quad swizzle (SMEM fits 5 buffers)
// Tiles, weight layouts, reductions, monolithic barrier: R11-verbatim.
// B=64, T=1024, D=256, H=512, BU=512, Z=768. 128 CTAs x 256 threads.
// ---------------------------------------------------------------------------

#define Bc   64
#define Tc   1024
#define Dc   256
#define Hc   512
#define ZC   768
#define NCTA 128
#define NTHR 256
#define ZBUF (128 * 64)                 // one chunk buffer (floats)
#define WA_SEC 196
#define WB_SEC 2056
#define REDB_SEC 320
#define SMEM_FLOATS (16*WA_SEC + 4*WB_SEC + 5*ZBUF + 256 + 8*REDB_SEC)
#define SMEM_BYTES  (SMEM_FLOATS * 4)

// -------------------- device-global state ----------------------------------
__device__ unsigned g_count = 0;
__device__ unsigned g_sense = 0;
__device__ __align__(256) float g_h [Hc * Bc];    // [col][b]
__device__ __align__(256) float g_bb[Hc * Bc];    // [col][b]
__device__ __align__(256) float g_xT[(size_t)Tc * Dc * Bc];   // [t][d][b]

// ------------------------------- helpers -----------------------------------
__device__ __forceinline__ void cp16(float* dst_smem, const float* src_gmem) {
    unsigned d = (unsigned)__cvta_generic_to_shared(dst_smem);
    asm volatile("cp.async.cg.shared.global [%0], [%1], 16;"
                 :: "r"(d), "l"(src_gmem) : "memory");
}
__device__ __forceinline__ void cp_commit() {
    asm volatile("cp.async.commit_group;" ::: "memory");
}
template <int N>
__device__ __forceinline__ void cp_wait() {
    asm volatile("cp.async.wait_group %0;" :: "n"(N) : "memory");
}

__device__ __forceinline__ void ffma2(unsigned long long& d,
                                      unsigned long long a,
                                      unsigned long long b) {
    asm("fma.rn.f32x2 %0, %1, %2, %0;" : "+l"(d) : "l"(a), "l"(b));
}
__device__ __forceinline__ void add2(unsigned long long& d,
                                     unsigned long long a,
                                     unsigned long long b) {
    asm("add.rn.f32x2 %0, %1, %2;" : "=l"(d) : "l"(a), "l"(b));
}
__device__ __forceinline__ unsigned long long dup2(float v) {
    unsigned long long r; unsigned u = __float_as_uint(v);
    asm("mov.b64 %0, {%1, %1};" : "=l"(r) : "r"(u));
    return r;
}
__device__ __forceinline__ float lo2(unsigned long long v) {
    return __uint_as_float((unsigned)v);
}
__device__ __forceinline__ float hi2(unsigned long long v) {
    return __uint_as_float((unsigned)(v >> 32));
}

__device__ __forceinline__ void mac16(unsigned long long* acc, float4 z,
                                      ulonglong2 w) {
    unsigned long long zz;
    zz = dup2(z.x); ffma2(acc[0], zz, w.x); ffma2(acc[1], zz, w.y);
    zz = dup2(z.y); ffma2(acc[2], zz, w.x); ffma2(acc[3], zz, w.y);
    zz = dup2(z.z); ffma2(acc[4], zz, w.x); ffma2(acc[5], zz, w.y);
    zz = dup2(z.w); ffma2(acc[6], zz, w.x); ffma2(acc[7], zz, w.y);
}

// ---- monolithic split global barrier (R8/R11 proven) ----
__device__ __forceinline__ void gbar_arrive(unsigned sense0, unsigned& ep) {
    __syncthreads();
    ep++;
    if (threadIdx.x == 0) {
        __threadfence();
        if (atomicAdd(&g_count, 1u) == (unsigned)(NCTA - 1)) {
            atomicExch(&g_count, 0u);
            asm volatile("st.release.gpu.u32 [%0], %1;"
                         :: "l"(&g_sense), "r"(sense0 + ep) : "memory");
        }
    }
}
__device__ __forceinline__ void gbar_wait(unsigned sense0, unsigned ep) {
    if (threadIdx.x == 0) {
        unsigned v, target = sense0 + ep;
        do {
            asm volatile("ld.acquire.gpu.u32 %0, [%1];"
                         : "=r"(v) : "l"(&g_sense) : "memory");
        } while (v != target);
    }
    __syncthreads();
}

// Stage one 128-row k-chunk into a 64-float-row buffer with XOR quad swizzle.
// Coalesced: each warp covers 2 full contiguous 256B gmem rows.
__device__ __forceinline__ void stage_chunk(float* buf,
                                            const float* __restrict__ src) {
    int tid = threadIdx.x;
#pragma unroll
    for (int i = 0; i < 8; i++) {
        int lin = tid + i * NTHR;           // 0..2047
        int l   = lin >> 4;                 // row 0..127
        int j   = lin & 15;                 // quad 0..15
        int f   = (l >> 3) & 7;
        cp16(buf + l * 64 + ((j ^ f) << 2), src + l * Bc + (j << 2));
    }
    cp_commit();
}

// Phase A: one chunk (8 k per thread), 4x4 tile. f = ks2&7 constant per thread.
__device__ __forceinline__ void gemmA_chunk(const float* __restrict__ buf,
                                            const float* __restrict__ wsec,
                                            int ks2, int rgA,
                                            unsigned long long* acc) {
    const float* zp = buf + (ks2 * 8) * 64 + ((rgA ^ (ks2 & 7)) << 2);
#pragma unroll
    for (int i = 0; i < 8; i++) {
        float4 z = *(const float4*)(zp + i * 64);
        ulonglong2 w = *(const ulonglong2*)(wsec + i * 4);
        mac16(acc, z, w);
    }
}

// Phase B: one chunk (32 k per thread), 4x4 tile. f constant per 8-row block.
__device__ __forceinline__ void gemmB_chunk(const float* __restrict__ buf,
                                            const float* __restrict__ wsec,
                                            int km, int rgB,
                                            unsigned long long* acc) {
#pragma unroll
    for (int j = 0; j < 4; j++) {
        int row0 = km * 32 + j * 8;
        const float* zp = buf + row0 * 64
                        + ((rgB ^ ((km * 4 + j) & 7)) << 2);
        const float* wp = wsec + j * 128;
#pragma unroll
        for (int i = 0; i < 8; i++) {
            float4 z = *(const float4*)(zp + i * 64);
            ulonglong2 w = *(const ulonglong2*)(wp + i * 16);
            mac16(acc, z, w);
        }
    }
}

// ------------------------- x transpose kernel ------------------------------
__global__ void __launch_bounds__(256) xpose_kernel(const float* __restrict__ x) {
    __shared__ float tile[32 * 65];
    int t = blockIdx.x;
    int tid = threadIdx.x;
    for (int dblk = 0; dblk < 8; dblk++) {
        int dl = tid & 31, bq = tid >> 5;
#pragma unroll
        for (int b8 = 0; b8 < 8; b8++) {
            int b = bq * 8 + b8;
            tile[dl * 65 + b] = x[((size_t)b * Tc + t) * Dc + dblk * 32 + dl];
        }
        __syncthreads();
        int b = tid & 63, dq = tid >> 6;
#pragma unroll
        for (int j = 0; j < 8; j++) {
            int d = dq * 8 + j;
            g_xT[((size_t)t * Dc + dblk * 32 + d) * Bc + b] = tile[d * 65 + b];
        }
        __syncthreads();
    }
}

// --------------------------------- kernel ----------------------------------
__global__ void __launch_bounds__(NTHR, 1)
cfc_persistent_kernel(const float* __restrict__ ts,
                      const float* __restrict__ h0,  const float* __restrict__ s0,
                      const float* __restrict__ Wbb, const float* __restrict__ bbb,
                      const float* __restrict__ Wff1,const float* __restrict__ bff1,
                      const float* __restrict__ Wff2,const float* __restrict__ bff2,
                      const float* __restrict__ Wta, const float* __restrict__ bta,
                      const float* __restrict__ Wtb, const float* __restrict__ btb,
                      float* __restrict__ out) {
    extern __shared__ float smem[];
    float* s_wA   = smem;                       // 16 x 196
    float* s_wB   = s_wA + 16 * WA_SEC;         // 4 x 2056
    float* s_z    = s_wB + 4 * WB_SEC;          // 5 x ZBUF
    float* s_redA = s_z + 5 * ZBUF;             // 256
    float* s_redB = s_redA + 256;               // 8 x 320

    const int tid = threadIdx.x;
    const int c0  = blockIdx.x * 4;
    const int lane = tid & 31, warp = tid >> 5;
    const int ks2 = tid & 15, rgA = tid >> 4;                      // phase A
    const int rgB = tid & 15, km = (tid >> 4) & 3, mB = tid >> 6;  // phase B
    const int ec = tid & 3, eb = tid >> 2;                         // epilogue
    const int cg = c0 + ec;
    const int eidxA = ((eb >> 2) << 4) + ((eb & 3) << 2) + ec;
    const int eoffB = (eb >> 2) * 20 + (eb & 3) * 4 + ec;

    // ---- one-time: weights -> sectioned SMEM (R11-exact layouts) ----
    for (int idx = tid; idx < ZC * 4; idx += NTHR) {
        int k = idx >> 2, cc = idx & 3;
        int sec = (k & 127) >> 3, ch = k >> 7, i = k & 7;
        s_wA[sec * WA_SEC + (ch * 8 + i) * 4 + cc] =
            __ldg(Wbb + (size_t)k * Hc + c0 + cc);
    }
    {
        const float* Wm[4] = {Wff1, Wff2, Wta, Wtb};
#pragma unroll
        for (int m = 0; m < 4; m++)
            for (int idx = tid; idx < Hc * 4; idx += NTHR) {
                int k = idx >> 2, cc = idx & 3;
                int sec = (k & 127) >> 5, ch = k >> 7, i = k & 31;
                s_wB[sec * WB_SEC + (ch * 32 + i) * 16 + m * 4 + cc] =
                    __ldg(Wm[m] + (size_t)k * Hc + c0 + cc);
            }
    }
    const float bbbc = __ldg(bbb  + cg);
    const float bf1c = __ldg(bff1 + cg);
    const float bf2c = __ldg(bff2 + cg);
    const float btac = __ldg(bta  + cg);
    const float btbc = __ldg(btb  + cg);

    float s_state = __ldg(s0 + (size_t)eb * Hc + cg);
    g_h[cg * Bc + eb] = __ldg(h0 + (size_t)eb * Hc + cg);

    float* sb0 = s_z;
    float* sb1 = s_z + ZBUF;
    float* sb2 = s_z + 2 * ZBUF;
    float* sb3 = s_z + 3 * ZBUF;
    float* sb4 = s_z + 4 * ZBUF;

    unsigned sense0 = 0, ep = 0;
    if (tid == 0) {
        asm volatile("ld.acquire.gpu.u32 %0, [%1];"
                     : "=r"(sense0) : "l"(&g_sense) : "memory");
    }

    gbar_arrive(sense0, ep);                    // publish h0
    // prefetch x(0): X0 -> sb0, X1 -> sb1 (2 outstanding groups at loop entry)
    stage_chunk(sb0, g_xT);
    stage_chunk(sb1, g_xT + (size_t)128 * Bc);

    for (int t = 0; t < Tc; t++) {
        // ============ Phase A: bb = silu(z @ Wbb + bbb), K=768 ============
        unsigned long long acc[8] = {0,0,0,0,0,0,0,0};
        // x pair first (no dependence on h) — one wait, one sync
        cp_wait<0>(); __syncthreads();
        gemmA_chunk(sb0, s_wA + ks2 * WA_SEC + 0 * 32, ks2, rgA, acc);  // X0
        gemmA_chunk(sb1, s_wA + ks2 * WA_SEC + 1 * 32, ks2, rgA, acc);  // X1
        gbar_wait(sense0, ep);                  // h(t) visible (has sync)
        stage_chunk(sb2, g_h);                  // H0
        stage_chunk(sb3, g_h + 128 * Bc);       // H1
        stage_chunk(sb4, g_h + 256 * Bc);       // H2
        stage_chunk(sb0, g_h + 384 * Bc);       // H3 (sb0 consumed pre-barrier)
        cp_wait<2>(); __syncthreads();
        gemmA_chunk(sb2, s_wA + ks2 * WA_SEC + 2 * 32, ks2, rgA, acc);  // H0
        gemmA_chunk(sb3, s_wA + ks2 * WA_SEC + 3 * 32, ks2, rgA, acc);  // H1
        cp_wait<0>(); __syncthreads();
        gemmA_chunk(sb4, s_wA + ks2 * WA_SEC + 4 * 32, ks2, rgA, acc);  // H2
        gemmA_chunk(sb0, s_wA + ks2 * WA_SEC + 5 * 32, ks2, rgA, acc);  // H3

        // reduce 16-way ksplit (lane bits 0..3) — R11-exact
#pragma unroll
        for (int d = 1; d <= 8; d <<= 1)
#pragma unroll
            for (int q = 0; q < 8; q++) {
                unsigned long long o = __shfl_xor_sync(0xffffffffu, acc[q], d);
                add2(acc[q], acc[q], o);
            }
        if ((tid & 15) == 0) {
            float* dst = s_redA + rgA * 16;
#pragma unroll
            for (int r = 0; r < 4; r++) {
                float4 v = make_float4(lo2(acc[2*r]), hi2(acc[2*r]),
                                       lo2(acc[2*r+1]), hi2(acc[2*r+1]));
                *(float4*)(dst + r * 4) = v;
            }
        }
        __syncthreads();
        {
            float av  = s_redA[eidxA] + bbbc;
            float bbv = av / (1.0f + expf(-av));       // silu
            g_bb[cg * Bc + eb] = bbv;
        }
        gbar_arrive(sense0, ep);                        // bb barrier
        float tstv = __ldg(ts + (size_t)eb * Tc + t);   // hidden under spin
        float tn   = 1.0f / tstv;
        float wts  = (tn > 0.0f) ? expf(tn * (1.0f - 2.0f * logf(tn))) : 0.0f;
        gbar_wait(sense0, ep);

        // ====== Phase B: 4 GEMMs over bb (K=512); gate & update ======
        unsigned long long fac[8] = {0,0,0,0,0,0,0,0};
        const int t1 = (t + 1 < Tc) ? t + 1 : t;
        stage_chunk(sb1, g_bb);                  // B0
        stage_chunk(sb2, g_bb + 128 * Bc);       // B1
        stage_chunk(sb3, g_bb + 256 * Bc);       // B2
        stage_chunk(sb4, g_bb + 384 * Bc);       // B3
        stage_chunk(sb0, g_xT + ((size_t)t1 * Dc) * Bc);        // X0(t+1)
        cp_wait<3>(); __syncthreads();
        gemmB_chunk(sb1, s_wB + km * WB_SEC + 0 * 512 + mB * 4, km, rgB, fac);
        gemmB_chunk(sb2, s_wB + km * WB_SEC + 1 * 512 + mB * 4, km, rgB, fac);
        cp_wait<1>(); __syncthreads();           // B2,B3 done; all past sb1
        stage_chunk(sb1, g_xT + ((size_t)t1 * Dc + 128) * Bc);  // X1(t+1)
        gemmB_chunk(sb3, s_wB + km * WB_SEC + 2 * 512 + mB * 4, km, rgB, fac);
        gemmB_chunk(sb4, s_wB + km * WB_SEC + 3 * 512 + mB * 4, km, rgB, fac);
        // outstanding: X0(t+1)@sb0, X1(t+1)@sb1 — matches loop entry

        // reduce km bit0 (lane bit 4), padded SMEM combine — R11-exact
#pragma unroll
        for (int q = 0; q < 8; q++) {
            unsigned long long o = __shfl_xor_sync(0xffffffffu, fac[q], 16);
            add2(fac[q], fac[q], o);
        }
        if (lane < 16) {
            float* dst = s_redB + ((warp & 1) * 4 + (warp >> 1)) * REDB_SEC
                       + lane * 20;
#pragma unroll
            for (int r = 0; r < 4; r++) {
                float4 v = make_float4(lo2(fac[2*r]), hi2(fac[2*r]),
                                       lo2(fac[2*r+1]), hi2(fac[2*r+1]));
                *(float4*)(dst + r * 4) = v;
            }
        }
        __syncthreads();
        {
            float p0 = s_redB[(0*4 + 0) * REDB_SEC + eoffB]
                     + s_redB[(1*4 + 0) * REDB_SEC + eoffB];
            float p1 = s_redB[(0*4 + 1) * REDB_SEC + eoffB]
                     + s_redB[(1*4 + 1) * REDB_SEC + eoffB];
            float p2 = s_redB[(0*4 + 2) * REDB_SEC + eoffB]
                     + s_redB[(1*4 + 2) * REDB_SEC + eoffB];
            float p3 = s_redB[(0*4 + 3) * REDB_SEC + eoffB]
                     + s_redB[(1*4 + 3) * REDB_SEC + eoffB];
            float ff1 = tanhf(p0 + bf1c);
            float ff2 = tanhf(p1 + bf2c);
            s_state += (p2 + btac) * wts + (p3 + btbc);
            float ti = 1.0f / (1.0f + expf(-s_state));
            float hn = ff1 + ti * (ff2 - ff1);
            g_h[cg * Bc + eb] = hn;
            out[((size_t)eb * Tc + t) * Hc + cg] = hn;
        }
        gbar_arrive(sense0, ep);                        // h barrier
    }
    cp_wait<0>();
}

// --------------------------------- launch ----------------------------------
extern "C" void kernel_launch(void* const* d_in, const int* in_sizes, int n_in,
                              void* d_out, int out_size) {
    (void)in_sizes; (void)n_in; (void)out_size;
    cudaFuncSetAttribute(cfc_persistent_kernel,
                         cudaFuncAttributeMaxDynamicSharedMemorySize, SMEM_BYTES);
    xpose_kernel<<<Tc, 256>>>((const float*)d_in[0]);
    cfc_persistent_kernel<<<NCTA, NTHR, SMEM_BYTES>>>(
        (const float*)d_in[1],
        (const float*)d_in[2],  (const float*)d_in[3],
        (const float*)d_in[4],  (const float*)d_in[5],
        (const float*)d_in[6],  (const float*)d_in[7],
        (const float*)d_in[8],  (const float*)d_in[9],
        (const float*)d_in[10], (const float*)d_in[11],
        (const float*)d_in[12], (const float*)d_in[13],
        (float*)d_out);
}

// round 15
// speedup vs baseline: 1.4367x; 1.0416x over previous
#include <cuda_runtime.h>
#include <cuda_bf16.h>
#include <math.h>

// ---------------------------------------------------------------------------
// CfC recurrence v10 = R14 (10.41ms) with 8-column phase-B thread tiles:
//   - thread computes 4 batch-rows x 8 cols (2 adjacent matrices), 8-way
//     k-split -> z LDS traffic halved (1.5 B/MAC), dup2 halved
//   - z addressing / swizzle / staging / schedule / barrier: R14-verbatim
// B=64, T=1024, D=256, H=512, BU=512, Z=768. 128 CTAs x 256 threads.
// ---------------------------------------------------------------------------

#define Bc   64
#define Tc   1024
#define Dc   256
#define Hc   512
#define ZC   768
#define NCTA 128
#define NTHR 256
#define ZBUF (128 * 64)                 // one chunk buffer (floats)
#define WA_SEC 196
#define WB_SEC 2056
#define REDB_SEC 320
#define SMEM_FLOATS (16*WA_SEC + 4*WB_SEC + 5*ZBUF + 256 + 16*REDB_SEC)
#define SMEM_BYTES  (SMEM_FLOATS * 4)   // 230,784 B < 232,448 B cap

// -------------------- device-global state ----------------------------------
__device__ unsigned g_count = 0;
__device__ unsigned g_sense = 0;
__device__ __align__(256) float g_h [Hc * Bc];    // [col][b]
__device__ __align__(256) float g_bb[Hc * Bc];    // [col][b]
__device__ __align__(256) float g_xT[(size_t)Tc * Dc * Bc];   // [t][d][b]

// ------------------------------- helpers -----------------------------------
__device__ __forceinline__ void cp16(float* dst_smem, const float* src_gmem) {
    unsigned d = (unsigned)__cvta_generic_to_shared(dst_smem);
    asm volatile("cp.async.cg.shared.global [%0], [%1], 16;"
                 :: "r"(d), "l"(src_gmem) : "memory");
}
__device__ __forceinline__ void cp_commit() {
    asm volatile("cp.async.commit_group;" ::: "memory");
}
template <int N>
__device__ __forceinline__ void cp_wait() {
    asm volatile("cp.async.wait_group %0;" :: "n"(N) : "memory");
}

__device__ __forceinline__ void ffma2(unsigned long long& d,
                                      unsigned long long a,
                                      unsigned long long b) {
    asm("fma.rn.f32x2 %0, %1, %2, %0;" : "+l"(d) : "l"(a), "l"(b));
}
__device__ __forceinline__ void add2(unsigned long long& d,
                                     unsigned long long a,
                                     unsigned long long b) {
    asm("add.rn.f32x2 %0, %1, %2;" : "=l"(d) : "l"(a), "l"(b));
}
__device__ __forceinline__ unsigned long long dup2(float v) {
    unsigned long long r; unsigned u = __float_as_uint(v);
    asm("mov.b64 %0, {%1, %1};" : "=l"(r) : "r"(u));
    return r;
}
__device__ __forceinline__ float lo2(unsigned long long v) {
    return __uint_as_float((unsigned)v);
}
__device__ __forceinline__ float hi2(unsigned long long v) {
    return __uint_as_float((unsigned)(v >> 32));
}

__device__ __forceinline__ void mac16(unsigned long long* acc, float4 z,
                                      ulonglong2 w) {
    unsigned long long zz;
    zz = dup2(z.x); ffma2(acc[0], zz, w.x); ffma2(acc[1], zz, w.y);
    zz = dup2(z.y); ffma2(acc[2], zz, w.x); ffma2(acc[3], zz, w.y);
    zz = dup2(z.z); ffma2(acc[4], zz, w.x); ffma2(acc[5], zz, w.y);
    zz = dup2(z.w); ffma2(acc[6], zz, w.x); ffma2(acc[7], zz, w.y);
}

// 4 rows x 8 cols (two matrices): one dup per z component, 16 FFMA2.
__device__ __forceinline__ void mac32(unsigned long long* a,
                                      unsigned long long* b, float4 z,
                                      ulonglong2 w0, ulonglong2 w1) {
    unsigned long long zz;
    zz = dup2(z.x);
    ffma2(a[0], zz, w0.x); ffma2(a[1], zz, w0.y);
    ffma2(b[0], zz, w1.x); ffma2(b[1], zz, w1.y);
    zz = dup2(z.y);
    ffma2(a[2], zz, w0.x); ffma2(a[3], zz, w0.y);
    ffma2(b[2], zz, w1.x); ffma2(b[3], zz, w1.y);
    zz = dup2(z.z);
    ffma2(a[4], zz, w0.x); ffma2(a[5], zz, w0.y);
    ffma2(b[4], zz, w1.x); ffma2(b[5], zz, w1.y);
    zz = dup2(z.w);
    ffma2(a[6], zz, w0.x); ffma2(a[7], zz, w0.y);
    ffma2(b[6], zz, w1.x); ffma2(b[7], zz, w1.y);
}

// ---- monolithic split global barrier (R8/R11/R14 proven) ----
__device__ __forceinline__ void gbar_arrive(unsigned sense0, unsigned& ep) {
    __syncthreads();
    ep++;
    if (threadIdx.x == 0) {
        __threadfence();
        if (atomicAdd(&g_count, 1u) == (unsigned)(NCTA - 1)) {
            atomicExch(&g_count, 0u);
            asm volatile("st.release.gpu.u32 [%0], %1;"
                         :: "l"(&g_sense), "r"(sense0 + ep) : "memory");
        }
    }
}
__device__ __forceinline__ void gbar_wait(unsigned sense0, unsigned ep) {
    if (threadIdx.x == 0) {
        unsigned v, target = sense0 + ep;
        do {
            asm volatile("ld.acquire.gpu.u32 %0, [%1];"
                         : "=r"(v) : "l"(&g_sense) : "memory");
        } while (v != target);
    }
    __syncthreads();
}

// Stage one 128-row k-chunk (R14-exact: coalesced, XOR quad swizzle).
__device__ __forceinline__ void stage_chunk(float* buf,
                                            const float* __restrict__ src) {
    int tid = threadIdx.x;
#pragma unroll
    for (int i = 0; i < 8; i++) {
        int lin = tid + i * NTHR;           // 0..2047
        int l   = lin >> 4;                 // row 0..127
        int j   = lin & 15;                 // quad 0..15
        int f   = (l >> 3) & 7;
        cp16(buf + l * 64 + ((j ^ f) << 2), src + l * Bc + (j << 2));
    }
    cp_commit();
}

// Phase A: one chunk (8 k per thread), 4x4 tile (R14-exact).
__device__ __forceinline__ void gemmA_chunk(const float* __restrict__ buf,
                                            const float* __restrict__ wsec,
                                            int ks2, int rgA,
                                            unsigned long long* acc) {
    const float* zp = buf + (ks2 * 8) * 64 + ((rgA ^ (ks2 & 7)) << 2);
#pragma unroll
    for (int i = 0; i < 8; i++) {
        float4 z = *(const float4*)(zp + i * 64);
        ulonglong2 w = *(const ulonglong2*)(wsec + i * 4);
        mac16(acc, z, w);
    }
}

// Phase B: one chunk, 16 k per thread (rows km*16..+15), 4x8 tile.
// wsec pre-offset: s_wB + (km>>1)*WB_SEC + ch*512 + (km&1)*256 + mB*8.
__device__ __forceinline__ void gemmB_chunk(const float* __restrict__ buf,
                                            const float* __restrict__ wsec,
                                            int km, int rgB,
                                            unsigned long long* fac) {
#pragma unroll
    for (int j = 0; j < 2; j++) {
        int row0 = km * 16 + j * 8;
        const float* zp = buf + row0 * 64
                        + ((rgB ^ ((km * 2 + j) & 7)) << 2);
        const float* wp = wsec + j * 128;
#pragma unroll
        for (int i = 0; i < 8; i++) {
            float4 z = *(const float4*)(zp + i * 64);
            ulonglong2 w0 = *(const ulonglong2*)(wp + i * 16);
            ulonglong2 w1 = *(const ulonglong2*)(wp + i * 16 + 4);
            mac32(fac, fac + 8, z, w0, w1);
        }
    }
}

// ------------------------- x transpose kernel ------------------------------
__global__ void __launch_bounds__(256) xpose_kernel(const float* __restrict__ x) {
    __shared__ float tile[32 * 65];
    int t = blockIdx.x;
    int tid = threadIdx.x;
    for (int dblk = 0; dblk < 8; dblk++) {
        int dl = tid & 31, bq = tid >> 5;
#pragma unroll
        for (int b8 = 0; b8 < 8; b8++) {
            int b = bq * 8 + b8;
            tile[dl * 65 + b] = x[((size_t)b * Tc + t) * Dc + dblk * 32 + dl];
        }
        __syncthreads();
        int b = tid & 63, dq = tid >> 6;
#pragma unroll
        for (int j = 0; j < 8; j++) {
            int d = dq * 8 + j;
            g_xT[((size_t)t * Dc + dblk * 32 + d) * Bc + b] = tile[d * 65 + b];
        }
        __syncthreads();
    }
}

// --------------------------------- kernel ----------------------------------
__global__ void __launch_bounds__(NTHR, 1)
cfc_persistent_kernel(const float* __restrict__ ts,
                      const float* __restrict__ h0,  const float* __restrict__ s0,
                      const float* __restrict__ Wbb, const float* __restrict__ bbb,
                      const float* __restrict__ Wff1,const float* __restrict__ bff1,
                      const float* __restrict__ Wff2,const float* __restrict__ bff2,
                      const float* __restrict__ Wta, const float* __restrict__ bta,
                      const float* __restrict__ Wtb, const float* __restrict__ btb,
                      float* __restrict__ out) {
    extern __shared__ float smem[];
    float* s_wA   = smem;                       // 16 x 196
    float* s_wB   = s_wA + 16 * WA_SEC;         // 4 x 2056
    float* s_z    = s_wB + 4 * WB_SEC;          // 5 x ZBUF
    float* s_redA = s_z + 5 * ZBUF;             // 256
    float* s_redB = s_redA + 256;               // 16 x 320

    const int tid = threadIdx.x;
    const int c0  = blockIdx.x * 4;
    const int lane = tid & 31, warp = tid >> 5;
    const int ks2 = tid & 15, rgA = tid >> 4;                      // phase A
    const int rgB = tid & 15, km = (tid >> 4) & 7, mB = tid >> 7;  // phase B
    const int ec = tid & 3, eb = tid >> 2;                         // epilogue
    const int cg = c0 + ec;
    const int eidxA = ((eb >> 2) << 4) + ((eb & 3) << 2) + ec;
    const int eoffB = (eb >> 2) * 20 + (eb & 3) * 4 + ec;

    // ---- one-time: weights -> sectioned SMEM (R11/R14-exact layouts) ----
    for (int idx = tid; idx < ZC * 4; idx += NTHR) {
        int k = idx >> 2, cc = idx & 3;
        int sec = (k & 127) >> 3, ch = k >> 7, i = k & 7;
        s_wA[sec * WA_SEC + (ch * 8 + i) * 4 + cc] =
            __ldg(Wbb + (size_t)k * Hc + c0 + cc);
    }
    {
        const float* Wm[4] = {Wff1, Wff2, Wta, Wtb};
#pragma unroll
        for (int m = 0; m < 4; m++)
            for (int idx = tid; idx < Hc * 4; idx += NTHR) {
                int k = idx >> 2, cc = idx & 3;
                int sec = (k & 127) >> 5, ch = k >> 7, i = k & 31;
                s_wB[sec * WB_SEC + (ch * 32 + i) * 16 + m * 4 + cc] =
                    __ldg(Wm[m] + (size_t)k * Hc + c0 + cc);
            }
    }
    const float bbbc = __ldg(bbb  + cg);
    const float bf1c = __ldg(bff1 + cg);
    const float bf2c = __ldg(bff2 + cg);
    const float btac = __ldg(bta  + cg);
    const float btbc = __ldg(btb  + cg);

    float s_state = __ldg(s0 + (size_t)eb * Hc + cg);
    g_h[cg * Bc + eb] = __ldg(h0 + (size_t)eb * Hc + cg);

    float* sb0 = s_z;
    float* sb1 = s_z + ZBUF;
    float* sb2 = s_z + 2 * ZBUF;
    float* sb3 = s_z + 3 * ZBUF;
    float* sb4 = s_z + 4 * ZBUF;

    unsigned sense0 = 0, ep = 0;
    if (tid == 0) {
        asm volatile("ld.acquire.gpu.u32 %0, [%1];"
                     : "=r"(sense0) : "l"(&g_sense) : "memory");
    }

    gbar_arrive(sense0, ep);                    // publish h0
    stage_chunk(sb0, g_xT);                     // X0
    stage_chunk(sb1, g_xT + (size_t)128 * Bc);  // X1

    for (int t = 0; t < Tc; t++) {
        // ============ Phase A: bb = silu(z @ Wbb + bbb), K=768 ============
        unsigned long long acc[8] = {0,0,0,0,0,0,0,0};
        cp_wait<0>(); __syncthreads();
        gemmA_chunk(sb0, s_wA + ks2 * WA_SEC + 0 * 32, ks2, rgA, acc);  // X0
        gemmA_chunk(sb1, s_wA + ks2 * WA_SEC + 1 * 32, ks2, rgA, acc);  // X1
        gbar_wait(sense0, ep);                  // h(t) visible (has sync)
        stage_chunk(sb2, g_h);                  // H0
        stage_chunk(sb3, g_h + 128 * Bc);       // H1
        stage_chunk(sb4, g_h + 256 * Bc);       // H2
        stage_chunk(sb0, g_h + 384 * Bc);       // H3
        cp_wait<2>(); __syncthreads();
        gemmA_chunk(sb2, s_wA + ks2 * WA_SEC + 2 * 32, ks2, rgA, acc);  // H0
        gemmA_chunk(sb3, s_wA + ks2 * WA_SEC + 3 * 32, ks2, rgA, acc);  // H1
        cp_wait<0>(); __syncthreads();
        gemmA_chunk(sb4, s_wA + ks2 * WA_SEC + 4 * 32, ks2, rgA, acc);  // H2
        gemmA_chunk(sb0, s_wA + ks2 * WA_SEC + 5 * 32, ks2, rgA, acc);  // H3

        // reduce 16-way ksplit (lane bits 0..3) — R14-exact
#pragma unroll
        for (int d = 1; d <= 8; d <<= 1)
#pragma unroll
            for (int q = 0; q < 8; q++) {
                unsigned long long o = __shfl_xor_sync(0xffffffffu, acc[q], d);
                add2(acc[q], acc[q], o);
            }
        if ((tid & 15) == 0) {
            float* dst = s_redA + rgA * 16;
#pragma unroll
            for (int r = 0; r < 4; r++) {
                float4 v = make_float4(lo2(acc[2*r]), hi2(acc[2*r]),
                                       lo2(acc[2*r+1]), hi2(acc[2*r+1]));
                *(float4*)(dst + r * 4) = v;
            }
        }
        __syncthreads();
        {
            float av  = s_redA[eidxA] + bbbc;
            float bbv = av / (1.0f + expf(-av));       // silu
            g_bb[cg * Bc + eb] = bbv;
        }
        gbar_arrive(sense0, ep);                        // bb barrier
        float tstv = __ldg(ts + (size_t)eb * Tc + t);   // hidden under spin
        float tn   = 1.0f / tstv;
        float wts  = (tn > 0.0f) ? expf(tn * (1.0f - 2.0f * logf(tn))) : 0.0f;
        gbar_wait(sense0, ep);

        // ====== Phase B: 4 GEMMs over bb (K=512), 4x8 tiles ======
        unsigned long long fac[16] = {0,0,0,0,0,0,0,0,0,0,0,0,0,0,0,0};
        const int t1 = (t + 1 < Tc) ? t + 1 : t;
        const float* wBbase = s_wB + (km >> 1) * WB_SEC + (km & 1) * 256
                            + mB * 8;
        stage_chunk(sb1, g_bb);                  // B0
        stage_chunk(sb2, g_bb + 128 * Bc);       // B1
        stage_chunk(sb3, g_bb + 256 * Bc);       // B2
        stage_chunk(sb4, g_bb + 384 * Bc);       // B3
        stage_chunk(sb0, g_xT + ((size_t)t1 * Dc) * Bc);        // X0(t+1)
        cp_wait<3>(); __syncthreads();
        gemmB_chunk(sb1, wBbase + 0 * 512, km, rgB, fac);
        gemmB_chunk(sb2, wBbase + 1 * 512, km, rgB, fac);
        cp_wait<1>(); __syncthreads();           // B2,B3 done; all past sb1
        stage_chunk(sb1, g_xT + ((size_t)t1 * Dc + 128) * Bc);  // X1(t+1)
        gemmB_chunk(sb3, wBbase + 2 * 512, km, rgB, fac);
        gemmB_chunk(sb4, wBbase + 3 * 512, km, rgB, fac);
        // outstanding: X0(t+1)@sb0, X1(t+1)@sb1 — matches loop entry

        // reduce km bit0 (lane bit 4), then SMEM combine over km bits 1-2
#pragma unroll
        for (int q = 0; q < 16; q++) {
            unsigned long long o = __shfl_xor_sync(0xffffffffu, fac[q], 16);
            add2(fac[q], fac[q], o);
        }
        if (lane < 16) {
            int kmHigh = warp & 3;
            int m0 = (warp >> 2) * 2;            // matrices m0, m0+1
            float* dst0 = s_redB + (kmHigh * 4 + m0) * REDB_SEC + lane * 20;
            float* dst1 = dst0 + REDB_SEC;
#pragma unroll
            for (int r = 0; r < 4; r++) {
                float4 v0 = make_float4(lo2(fac[2*r]), hi2(fac[2*r]),
                                        lo2(fac[2*r+1]), hi2(fac[2*r+1]));
                *(float4*)(dst0 + r * 4) = v0;
                float4 v1 = make_float4(lo2(fac[8+2*r]), hi2(fac[8+2*r]),
                                        lo2(fac[8+2*r+1]), hi2(fac[8+2*r+1]));
                *(float4*)(dst1 + r * 4) = v1;
            }
        }
        __syncthreads();
        {
            float p0 = 0.f, p1 = 0.f, p2 = 0.f, p3 = 0.f;
#pragma unroll
            for (int kh = 0; kh < 4; kh++) {
                p0 += s_redB[(kh * 4 + 0) * REDB_SEC + eoffB];
                p1 += s_redB[(kh * 4 + 1) * REDB_SEC + eoffB];
                p2 += s_redB[(kh * 4 + 2) * REDB_SEC + eoffB];
                p3 += s_redB[(kh * 4 + 3) * REDB_SEC + eoffB];
            }
            float ff1 = tanhf(p0 + bf1c);
            float ff2 = tanhf(p1 + bf2c);
            s_state += (p2 + btac) * wts + (p3 + btbc);
            float ti = 1.0f / (1.0f + expf(-s_state));
            float hn = ff1 + ti * (ff2 - ff1);
            g_h[cg * Bc + eb] = hn;
            out[((size_t)eb * Tc + t) * Hc + cg] = hn;
        }
        gbar_arrive(sense0, ep);                        // h barrier
    }
    cp_wait<0>();
}

// --------------------------------- launch ----------------------------------
extern "C" void kernel_launch(void* const* d_in, const int* in_sizes, int n_in,
                              void* d_out, int out_size) {
    (void)in_sizes; (void)n_in; (void)out_size;
    cudaFuncSetAttribute(cfc_persistent_kernel,
                         cudaFuncAttributeMaxDynamicSharedMemorySize, SMEM_BYTES);
    xpose_kernel<<<Tc, 256>>>((const float*)d_in[0]);
    cfc_persistent_kernel<<<NCTA, NTHR, SMEM_BYTES>>>(
        (const float*)d_in[1],
        (const float*)d_in[2],  (const float*)d_in[3],
        (const float*)d_in[4],  (const float*)d_in[5],
        (const float*)d_in[6],  (const float*)d_in[7],
        (const float*)d_in[8],  (const float*)d_in[9],
        (const float*)d_in[10], (const float*)d_in[11],
        (const float*)d_in[12], (const float*)d_in[13],
        (float*)d_out);
}

// round 16
// speedup vs baseline: 1.5249x; 1.0614x over previous
#include <cuda_runtime.h>
#include <cuda_bf16.h>
#include <math.h>

// ---------------------------------------------------------------------------
// CfC recurrence v11 = R15 (9.99ms) restructured warp-autonomous:
//   - k-split assigned per warp (ks = 2w+b4): each warp stages & consumes ONLY
//     its own 16 rows of every chunk -> no __syncthreads in the GEMM pipeline
//   - phase B: 4 rows x 16 cols per thread (all 4 matrices), z LDS 1x
//   - new bank-skewed s_wB layout (544-float 32-row blocks, +8 per 8-row grp)
//   - one shfl + 8-section SMEM reduction per phase; 4-buffer ring w/ swap
// B=64, T=1024, D=256, H=512, BU=512, Z=768. 128 CTAs x 256 threads.
// ---------------------------------------------------------------------------

#define Bc   64
#define Tc   1024
#define Dc   256
#define Hc   512
#define ZC   768
#define NCTA 128
#define NTHR 256
#define ZBUF (128 * 64)
#define WA_SEC 196
#define REDA_SEC 320
#define REDB_SEC 1088
#define OFF_WB   (16 * WA_SEC)                 // 3136
#define OFF_Z    (OFF_WB + 8704)               // 11840
#define OFF_RA   (OFF_Z + 4 * ZBUF)            // 44608
#define OFF_RB   (OFF_RA + 8 * REDA_SEC)       // 47168
#define SMEM_FLOATS (OFF_RB + 8 * REDB_SEC)    // 55872
#define SMEM_BYTES  (SMEM_FLOATS * 4)          // 223,488 B

// -------------------- device-global state ----------------------------------
__device__ unsigned g_count = 0;
__device__ unsigned g_sense = 0;
__device__ __align__(256) float g_h [Hc * Bc];    // [col][b]
__device__ __align__(256) float g_bb[Hc * Bc];    // [col][b]
__device__ __align__(256) float g_xT[(size_t)Tc * Dc * Bc];   // [t][d][b]

// ------------------------------- helpers -----------------------------------
__device__ __forceinline__ void cp16(float* dst_smem, const float* src_gmem) {
    unsigned d = (unsigned)__cvta_generic_to_shared(dst_smem);
    asm volatile("cp.async.cg.shared.global [%0], [%1], 16;"
                 :: "r"(d), "l"(src_gmem) : "memory");
}
__device__ __forceinline__ void cp_commit() {
    asm volatile("cp.async.commit_group;" ::: "memory");
}
template <int N>
__device__ __forceinline__ void cp_wait() {
    asm volatile("cp.async.wait_group %0;" :: "n"(N) : "memory");
}

__device__ __forceinline__ void ffma2(unsigned long long& d,
                                      unsigned long long a,
                                      unsigned long long b) {
    asm("fma.rn.f32x2 %0, %1, %2, %0;" : "+l"(d) : "l"(a), "l"(b));
}
__device__ __forceinline__ void add2(unsigned long long& d,
                                     unsigned long long a,
                                     unsigned long long b) {
    asm("add.rn.f32x2 %0, %1, %2;" : "=l"(d) : "l"(a), "l"(b));
}
__device__ __forceinline__ unsigned long long dup2(float v) {
    unsigned long long r; unsigned u = __float_as_uint(v);
    asm("mov.b64 %0, {%1, %1};" : "=l"(r) : "r"(u));
    return r;
}
__device__ __forceinline__ float lo2(unsigned long long v) {
    return __uint_as_float((unsigned)v);
}
__device__ __forceinline__ float hi2(unsigned long long v) {
    return __uint_as_float((unsigned)(v >> 32));
}

__device__ __forceinline__ void mac16(unsigned long long* acc, float4 z,
                                      ulonglong2 w) {
    unsigned long long zz;
    zz = dup2(z.x); ffma2(acc[0], zz, w.x); ffma2(acc[1], zz, w.y);
    zz = dup2(z.y); ffma2(acc[2], zz, w.x); ffma2(acc[3], zz, w.y);
    zz = dup2(z.z); ffma2(acc[4], zz, w.x); ffma2(acc[5], zz, w.y);
    zz = dup2(z.w); ffma2(acc[6], zz, w.x); ffma2(acc[7], zz, w.y);
}

// one z value (dup'd) times 16 weight cols -> 8 FFMA2
__device__ __forceinline__ void macrow(unsigned long long* a,
                                       unsigned long long zz,
                                       ulonglong2 w0, ulonglong2 w1,
                                       ulonglong2 w2, ulonglong2 w3) {
    ffma2(a[0], zz, w0.x); ffma2(a[1], zz, w0.y);
    ffma2(a[2], zz, w1.x); ffma2(a[3], zz, w1.y);
    ffma2(a[4], zz, w2.x); ffma2(a[5], zz, w2.y);
    ffma2(a[6], zz, w3.x); ffma2(a[7], zz, w3.y);
}

// ---- monolithic split global barrier (R8..R15 proven) ----
__device__ __forceinline__ void gbar_arrive(unsigned sense0, unsigned& ep) {
    __syncthreads();
    ep++;
    if (threadIdx.x == 0) {
        __threadfence();
        if (atomicAdd(&g_count, 1u) == (unsigned)(NCTA - 1)) {
            atomicExch(&g_count, 0u);
            asm volatile("st.release.gpu.u32 [%0], %1;"
                         :: "l"(&g_sense), "r"(sense0 + ep) : "memory");
        }
    }
}
__device__ __forceinline__ void gbar_wait(unsigned sense0, unsigned ep) {
    if (threadIdx.x == 0) {
        unsigned v, target = sense0 + ep;
        do {
            asm volatile("ld.acquire.gpu.u32 %0, [%1];"
                         : "=r"(v) : "l"(&g_sense) : "memory");
        } while (v != target);
    }
    __syncthreads();
}

// Stage THIS WARP's 16-row slice of a 128-row chunk (rows 16w..16w+15).
// Coalesced (each wavefront = 2 contiguous 256B rows); XOR quad swizzle.
__device__ __forceinline__ void stage_slice(float* buf,
                                            const float* __restrict__ src,
                                            int w) {
    int lane = threadIdx.x & 31;
#pragma unroll
    for (int i = 0; i < 8; i++) {
        int lin = lane + i * 32;            // 0..255
        int l   = w * 16 + (lin >> 4);      // row in chunk
        int j   = lin & 15;                 // quad
        int f   = (l >> 3) & 7;
        cp16(buf + l * 64 + ((j ^ f) << 2), src + l * Bc + (j << 2));
    }
    cp_commit();
}

// Phase A: one chunk, 8 k per thread (rows ks*8..+7), 4x4 tile.
__device__ __forceinline__ void gemmA_chunk(const float* __restrict__ buf,
                                            const float* __restrict__ wsec,
                                            int ks, int rgA,
                                            unsigned long long* acc) {
    const float* zp = buf + (ks * 8) * 64 + ((rgA ^ (ks & 7)) << 2);
#pragma unroll
    for (int i = 0; i < 8; i++) {
        float4 z = *(const float4*)(zp + i * 64);
        ulonglong2 w = *(const ulonglong2*)(wsec + i * 4);
        mac16(acc, z, w);
    }
}

// Phase B: one chunk, 8 k per thread (rows km*8..+7), 4 rows x 16 cols.
// wch = s_wB + ch*2176. Per-k weight row: 16 floats (4 matrices x 4 cols).
__device__ __forceinline__ void gemmB_chunk(const float* __restrict__ buf,
                                            const float* __restrict__ wch,
                                            int km, int rgB,
                                            unsigned long long* acc) {
    const float* zp = buf + (km * 8) * 64 + ((rgB ^ (km & 7)) << 2);
    const float* wp = wch + (km >> 2) * 544 + ((km & 3) * 8) * 16
                    + (km & 3) * 8;
#pragma unroll
    for (int i = 0; i < 8; i++) {
        float4 z = *(const float4*)(zp + i * 64);
        const ulonglong2* w = (const ulonglong2*)(wp + i * 16);
        ulonglong2 w0 = w[0], w1 = w[1], w2 = w[2], w3 = w[3];
        macrow(acc +  0, dup2(z.x), w0, w1, w2, w3);
        macrow(acc +  8, dup2(z.y), w0, w1, w2, w3);
        macrow(acc + 16, dup2(z.z), w0, w1, w2, w3);
        macrow(acc + 24, dup2(z.w), w0, w1, w2, w3);
    }
}

// ------------------------- x transpose kernel ------------------------------
__global__ void __launch_bounds__(256) xpose_kernel(const float* __restrict__ x) {
    __shared__ float tile[32 * 65];
    int t = blockIdx.x;
    int tid = threadIdx.x;
    for (int dblk = 0; dblk < 8; dblk++) {
        int dl = tid & 31, bq = tid >> 5;
#pragma unroll
        for (int b8 = 0; b8 < 8; b8++) {
            int b = bq * 8 + b8;
            tile[dl * 65 + b] = x[((size_t)b * Tc + t) * Dc + dblk * 32 + dl];
        }
        __syncthreads();
        int b = tid & 63, dq = tid >> 6;
#pragma unroll
        for (int j = 0; j < 8; j++) {
            int d = dq * 8 + j;
            g_xT[((size_t)t * Dc + dblk * 32 + d) * Bc + b] = tile[d * 65 + b];
        }
        __syncthreads();
    }
}

// --------------------------------- kernel ----------------------------------
__global__ void __launch_bounds__(NTHR, 1)
cfc_persistent_kernel(const float* __restrict__ ts,
                      const float* __restrict__ h0,  const float* __restrict__ s0,
                      const float* __restrict__ Wbb, const float* __restrict__ bbb,
                      const float* __restrict__ Wff1,const float* __restrict__ bff1,
                      const float* __restrict__ Wff2,const float* __restrict__ bff2,
                      const float* __restrict__ Wta, const float* __restrict__ bta,
                      const float* __restrict__ Wtb, const float* __restrict__ btb,
                      float* __restrict__ out) {
    extern __shared__ float smem[];
    float* s_wA   = smem;                       // 16 x 196
    float* s_wB   = smem + OFF_WB;              // 4 chunks x 2176
    float* s_z    = smem + OFF_Z;               // 4 x ZBUF
    float* s_redA = smem + OFF_RA;              // 8 x 320
    float* s_redB = smem + OFF_RB;              // 8 x 1088

    const int tid = threadIdx.x;
    const int c0  = blockIdx.x * 4;
    const int lane = tid & 31, wrp = tid >> 5;
    const int b4  = lane >> 4;                  // k-split low bit
    const int ks  = (wrp << 1) | b4;            // phase A/B k-split (0..15)
    const int rg  = lane & 15;                  // row group (both phases)
    const int ec = tid & 3, eb = tid >> 2;      // epilogue ids
    const int cg = c0 + ec;
    const int eoff = (eb >> 2) * 20 + (eb & 3) * 4 + ec;           // redA
    const int eoffB = (eb >> 2) * 68 + (eb & 3) * 4 + ec;          // redB (+m*16)

    // ---- one-time: weights -> SMEM ----
    for (int idx = tid; idx < ZC * 4; idx += NTHR) {
        int k = idx >> 2, cc = idx & 3;
        int sec = (k & 127) >> 3, ch = k >> 7, i = k & 7;
        s_wA[sec * WA_SEC + (ch * 8 + i) * 4 + cc] =
            __ldg(Wbb + (size_t)k * Hc + c0 + cc);
    }
    {
        const float* Wm[4] = {Wff1, Wff2, Wta, Wtb};
#pragma unroll
        for (int m = 0; m < 4; m++)
            for (int idx = tid; idx < Hc * 4; idx += NTHR) {
                int k = idx >> 2, cc = idx & 3;
                int ch = k >> 7, kl = k & 127;
                int addr = ch * 2176 + (kl >> 5) * 544 + (kl & 31) * 16
                         + ((kl >> 3) & 3) * 8 + m * 4 + cc;
                s_wB[addr] = __ldg(Wm[m] + (size_t)k * Hc + c0 + cc);
            }
    }
    const float bbbc = __ldg(bbb  + cg);
    const float bf1c = __ldg(bff1 + cg);
    const float bf2c = __ldg(bff2 + cg);
    const float btac = __ldg(bta  + cg);
    const float btbc = __ldg(btb  + cg);

    float s_state = __ldg(s0 + (size_t)eb * Hc + cg);
    g_h[cg * Bc + eb] = __ldg(h0 + (size_t)eb * Hc + cg);

    float* p0 = s_z;
    float* p1 = s_z + ZBUF;
    float* p2 = s_z + 2 * ZBUF;
    float* p3 = s_z + 3 * ZBUF;

    unsigned sense0 = 0, ep = 0;
    if (tid == 0) {
        asm volatile("ld.acquire.gpu.u32 %0, [%1];"
                     : "=r"(sense0) : "l"(&g_sense) : "memory");
    }

    gbar_arrive(sense0, ep);                    // publish h0 (epoch 1)
    stage_slice(p0, g_xT, wrp);                 // X0 slice
    stage_slice(p1, g_xT + (size_t)128 * Bc, wrp);  // X1 slice

    for (int t = 0; t < Tc; t++) {
        // ============ Phase A: bb = silu(z @ Wbb + bbb), K=768 ============
        unsigned long long acc[8] = {0,0,0,0,0,0,0,0};
        cp_wait<0>();                            // own X slices ready
        gemmA_chunk(p0, s_wA + ks * WA_SEC + 0 * 32, ks, rg, acc);  // X0
        gemmA_chunk(p1, s_wA + ks * WA_SEC + 1 * 32, ks, rg, acc);  // X1
        gbar_wait(sense0, ep);                   // h(t) visible chip-wide
        stage_slice(p2, g_h, wrp);               // H0
        stage_slice(p3, g_h + 128 * Bc, wrp);    // H1
        stage_slice(p0, g_h + 256 * Bc, wrp);    // H2
        stage_slice(p1, g_h + 384 * Bc, wrp);    // H3
        cp_wait<2>();
        gemmA_chunk(p2, s_wA + ks * WA_SEC + 2 * 32, ks, rg, acc);  // H0
        gemmA_chunk(p3, s_wA + ks * WA_SEC + 3 * 32, ks, rg, acc);  // H1
        cp_wait<0>();
        gemmA_chunk(p0, s_wA + ks * WA_SEC + 4 * 32, ks, rg, acc);  // H2
        gemmA_chunk(p1, s_wA + ks * WA_SEC + 5 * 32, ks, rg, acc);  // H3

        // reduce k-split low bit (lane bit 4), then store warp section
#pragma unroll
        for (int q = 0; q < 8; q++) {
            unsigned long long o = __shfl_xor_sync(0xffffffffu, acc[q], 16);
            add2(acc[q], acc[q], o);
        }
        if (lane < 16) {
            float* dst = s_redA + wrp * REDA_SEC + rg * 20;
#pragma unroll
            for (int r = 0; r < 4; r++) {
                float4 v = make_float4(lo2(acc[2*r]), hi2(acc[2*r]),
                                       lo2(acc[2*r+1]), hi2(acc[2*r+1]));
                *(float4*)(dst + r * 4) = v;
            }
        }
        __syncthreads();
        {
            float av = bbbc;
#pragma unroll
            for (int kh = 0; kh < 8; kh++)
                av += s_redA[kh * REDA_SEC + eoff];
            float bbv = av / (1.0f + expf(-av));       // silu
            g_bb[cg * Bc + eb] = bbv;
        }
        gbar_arrive(sense0, ep);                        // bb barrier
        float tstv = __ldg(ts + (size_t)eb * Tc + t);   // hidden under spin
        float tn   = 1.0f / tstv;
        float wts  = (tn > 0.0f) ? expf(tn * (1.0f - 2.0f * logf(tn))) : 0.0f;
        gbar_wait(sense0, ep);

        // ====== Phase B: 4 GEMMs over bb (K=512), 4x16 tiles ======
        unsigned long long fac[32];
#pragma unroll
        for (int q = 0; q < 32; q++) fac[q] = 0ull;
        const int t1 = (t + 1 < Tc) ? t + 1 : t;
        stage_slice(p2, g_bb, wrp);              // B0
        stage_slice(p3, g_bb + 128 * Bc, wrp);   // B1
        stage_slice(p0, g_bb + 256 * Bc, wrp);   // B2
        stage_slice(p1, g_bb + 384 * Bc, wrp);   // B3
        cp_wait<2>();
        gemmB_chunk(p2, s_wB + 0 * 2176, ks, rg, fac);  // B0
        gemmB_chunk(p3, s_wB + 1 * 2176, ks, rg, fac);  // B1
        stage_slice(p2, g_xT + ((size_t)t1 * Dc) * Bc, wrp);        // X0'
        stage_slice(p3, g_xT + ((size_t)t1 * Dc + 128) * Bc, wrp);  // X1'
        cp_wait<2>();                            // B2,B3 done; X' pending
        gemmB_chunk(p0, s_wB + 2 * 2176, ks, rg, fac);  // B2
        gemmB_chunk(p1, s_wB + 3 * 2176, ks, rg, fac);  // B3

        // reduce k-split low bit, store warp section (8 kmHigh sections)
#pragma unroll
        for (int q = 0; q < 32; q++) {
            unsigned long long o = __shfl_xor_sync(0xffffffffu, fac[q], 16);
            add2(fac[q], fac[q], o);
        }
        if (lane < 16) {
            float* dst = s_redB + wrp * REDB_SEC + rg * 68;
#pragma unroll
            for (int r = 0; r < 4; r++)
#pragma unroll
                for (int m = 0; m < 4; m++) {
                    unsigned long long a0 = fac[r * 8 + m * 2];
                    unsigned long long a1 = fac[r * 8 + m * 2 + 1];
                    float4 v = make_float4(lo2(a0), hi2(a0), lo2(a1), hi2(a1));
                    *(float4*)(dst + m * 16 + r * 4) = v;
                }
        }
        __syncthreads();
        {
            float p[4] = {0.f, 0.f, 0.f, 0.f};
#pragma unroll
            for (int kh = 0; kh < 8; kh++) {
                const float* srcp = s_redB + kh * REDB_SEC + eoffB;
#pragma unroll
                for (int m = 0; m < 4; m++) p[m] += srcp[m * 16];
            }
            float ff1 = tanhf(p[0] + bf1c);
            float ff2 = tanhf(p[1] + bf2c);
            s_state += (p[2] + btac) * wts + (p[3] + btbc);
            float ti = 1.0f / (1.0f + expf(-s_state));
            float hn = ff1 + ti * (ff2 - ff1);
            g_h[cg * Bc + eb] = hn;
            out[((size_t)eb * Tc + t) * Hc + cg] = hn;
        }
        gbar_arrive(sense0, ep);                        // h barrier
        // swap: X'@p2,p3 become next step's p0,p1
        float* tA = p0; p0 = p2; p2 = tA;
        float* tB = p1; p1 = p3; p3 = tB;
    }
    cp_wait<0>();
}

// --------------------------------- launch ----------------------------------
extern "C" void kernel_launch(void* const* d_in, const int* in_sizes, int n_in,
                              void* d_out, int out_size) {
    (void)in_sizes; (void)n_in; (void)out_size;
    cudaFuncSetAttribute(cfc_persistent_kernel,
                         cudaFuncAttributeMaxDynamicSharedMemorySize, SMEM_BYTES);
    xpose_kernel<<<Tc, 256>>>((const float*)d_in[0]);
    cfc_persistent_kernel<<<NCTA, NTHR, SMEM_BYTES>>>(
        (const float*)d_in[1],
        (const float*)d_in[2],  (const float*)d_in[3],
        (const float*)d_in[4],  (const float*)d_in[5],
        (const float*)d_in[6],  (const float*)d_in[7],
        (const float*)d_in[8],  (const float*)d_in[9],
        (const float*)d_in[10], (const float*)d_in[11],
        (const float*)d_in[12], (const float*)d_in[13],
        (float*)d_out);
}